// round 4
// baseline (speedup 1.0000x reference)
#include <cuda_runtime.h>

// Problem shape (fixed by the dataset)
#define BB 4
#define NN 8192
#define MM 2048
#define FF 256
#define KK 16
#define CH (3 + FF)   // 259 output channels

// Scratch (static __device__ — no allocations allowed)
__device__ float4 g_pts4[BB * NN];          // packed xyz point cloud, 512KB
__device__ int    g_idx [BB * MM * KK];     // neighbor indices
__device__ float  g_w   [BB * MM * KK];     // softmax weights
__device__ float  g_T   [(size_t)BB * NN * FF];  // features transposed (B,N,F), 33.5MB
__device__ float  g_outT[(size_t)BB * MM * FF];  // output features (B,M,F), 8MB

// ---------------------------------------------------------------------------
// K0: pack point cloud (B,3,N) -> float4 (B,N) for single-LDG.128 streaming
// ---------------------------------------------------------------------------
__global__ void k_pack(const float* __restrict__ pc) {
    int i = blockIdx.x * blockDim.x + threadIdx.x;
    if (i >= BB * NN) return;
    int b = i / NN, n = i - b * NN;
    const float* base = pc + (size_t)b * 3 * NN;
    g_pts4[i] = make_float4(base[n], base[NN + n], base[2 * NN + n], 0.0f);
}

// ---------------------------------------------------------------------------
// K1: warp-per-query KNN (k=16) + softmax weights + projected points.
// Lanes 0..15 hold a distributed ascending-sorted (dist, idx) list.
// ---------------------------------------------------------------------------
__global__ void k_knn(const float* __restrict__ qc,
                      const float* __restrict__ temp,
                      float* __restrict__ out) {
    const unsigned FULL = 0xFFFFFFFFu;
    int gw   = (blockIdx.x * blockDim.x + threadIdx.x) >> 5;  // global warp = query id
    int lane = threadIdx.x & 31;
    int b = gw / MM, m = gw - b * MM;

    const float* qb = qc + (size_t)b * 3 * MM;
    float qx = qb[m], qy = qb[MM + m], qz = qb[2 * MM + m];

    const float4* pts = g_pts4 + (size_t)b * NN;

    float ld  = __int_as_float(0x7f800000);  // +inf
    int   li  = 0;
    float tau = ld;                          // current worst of the 16 (list[15])

    for (int base = 0; base < NN; base += 32) {
        float4 p = pts[base + lane];
        float dx = p.x - qx, dy = p.y - qy, dz = p.z - qz;
        float d  = fmaf(dx, dx, fmaf(dy, dy, dz * dz));

        unsigned ball = __ballot_sync(FULL, d < tau);
        while (ball) {                       // warp-uniform loop
            int src = __ffs(ball) - 1;
            ball &= ball - 1;
            float dc = __shfl_sync(FULL, d, src);
            if (dc < tau) {                  // tau may have tightened; uniform branch
                int ic = base + src;
                unsigned less = __ballot_sync(FULL, (lane < KK) && (ld < dc));
                int pos = __popc(less);      // insertion position (<= 15 guaranteed)
                float pld = __shfl_up_sync(FULL, ld, 1);
                int   pli = __shfl_up_sync(FULL, li, 1);
                if (lane < KK) {
                    if (lane > pos)      { ld = pld; li = pli; }
                    else if (lane == pos){ ld = dc;  li = ic;  }
                }
                tau = __shfl_sync(FULL, ld, KK - 1);
            }
        }
    }

    // softmax(-d/sigma) over the 16 neighbors
    float tv    = *temp;
    float sigma = fmaxf(tv * tv, 1e-4f);
    float dmin  = __shfl_sync(FULL, ld, 0);  // list ascending -> lane0 is min
    float e = (lane < KK) ? __expf((dmin - ld) / sigma) : 0.0f;
    float s = e;
    #pragma unroll
    for (int off = 16; off >= 1; off >>= 1) s += __shfl_xor_sync(FULL, s, off);
    float w = e / s;

    if (lane < KK) {
        g_idx[gw * KK + lane] = li;
        g_w  [gw * KK + lane] = w;
    }

    // projected points = sum_j w_j * p_j
    float4 gp = make_float4(0.f, 0.f, 0.f, 0.f);
    if (lane < KK) gp = pts[li];
    float sx = w * gp.x, sy = w * gp.y, sz = w * gp.z;
    #pragma unroll
    for (int off = 16; off >= 1; off >>= 1) {
        sx += __shfl_xor_sync(FULL, sx, off);
        sy += __shfl_xor_sync(FULL, sy, off);
        sz += __shfl_xor_sync(FULL, sz, off);
    }
    if (lane == 0) {
        float* ob = out + (size_t)b * CH * MM;
        ob[m]           = sx;
        ob[MM + m]      = sy;
        ob[2 * MM + m]  = sz;
    }
}

// ---------------------------------------------------------------------------
// K2: transpose features (B,F,N) -> (B,N,F), tiled 32x32
// ---------------------------------------------------------------------------
__global__ void k_transpose(const float* __restrict__ feat) {
    __shared__ float tile[32][33];
    int b  = blockIdx.z;
    int n0 = blockIdx.x * 32, f0 = blockIdx.y * 32;
    const float* fb = feat + (size_t)b * FF * NN;
    #pragma unroll
    for (int yy = threadIdx.y; yy < 32; yy += 8)
        tile[yy][threadIdx.x] = fb[(size_t)(f0 + yy) * NN + n0 + threadIdx.x];
    __syncthreads();
    float* Tb = g_T + (size_t)b * NN * FF;
    #pragma unroll
    for (int yy = threadIdx.y; yy < 32; yy += 8)
        Tb[(size_t)(n0 + yy) * FF + f0 + threadIdx.x] = tile[threadIdx.x][yy];
}

// ---------------------------------------------------------------------------
// K3: weighted feature gather. One block per query, thread = feature.
// Rows of g_T are contiguous -> fully coalesced 128B gathers from L2.
// ---------------------------------------------------------------------------
__global__ void k_gather() {
    __shared__ int   sidx[KK];
    __shared__ float sw  [KK];
    int q = blockIdx.x;           // b*M + m
    int b = q / MM;
    if (threadIdx.x < KK) {
        sidx[threadIdx.x] = g_idx[q * KK + threadIdx.x];
        sw  [threadIdx.x] = g_w  [q * KK + threadIdx.x];
    }
    __syncthreads();
    int f = threadIdx.x;
    const float* Tb = g_T + (size_t)b * NN * FF;
    float acc = 0.0f;
    #pragma unroll
    for (int j = 0; j < KK; j++)
        acc = fmaf(sw[j], Tb[(size_t)sidx[j] * FF + f], acc);
    g_outT[(size_t)q * FF + f] = acc;
}

// ---------------------------------------------------------------------------
// K4: (B,M,F) -> output channels 3..258 of (B,259,M), tiled transpose
// ---------------------------------------------------------------------------
__global__ void k_out(float* __restrict__ out) {
    __shared__ float tile[32][33];
    int b  = blockIdx.z;
    int m0 = blockIdx.x * 32, f0 = blockIdx.y * 32;
    const float* ob = g_outT + (size_t)b * MM * FF;
    #pragma unroll
    for (int yy = threadIdx.y; yy < 32; yy += 8)
        tile[yy][threadIdx.x] = ob[(size_t)(m0 + yy) * FF + f0 + threadIdx.x];
    __syncthreads();
    float* dst = out + (size_t)b * CH * MM;
    #pragma unroll
    for (int yy = threadIdx.y; yy < 32; yy += 8)
        dst[(size_t)(3 + f0 + yy) * MM + m0 + threadIdx.x] = tile[threadIdx.x][yy];
}

// ---------------------------------------------------------------------------
extern "C" void kernel_launch(void* const* d_in, const int* in_sizes, int n_in,
                              void* d_out, int out_size) {
    (void)in_sizes; (void)n_in; (void)out_size;
    const float* pc   = (const float*)d_in[0];  // (B,3,N)
    const float* qc   = (const float*)d_in[1];  // (B,3,M)
    const float* feat = (const float*)d_in[2];  // (B,F,N)
    const float* temp = (const float*)d_in[3];  // scalar
    float* out = (float*)d_out;                 // (B,259,M)

    k_pack<<<(BB * NN + 255) / 256, 256>>>(pc);
    k_knn<<<(BB * MM) / 8, 256>>>(qc, temp, out);
    k_transpose<<<dim3(NN / 32, FF / 32, BB), dim3(32, 8)>>>(feat);
    k_gather<<<BB * MM, FF>>>();
    k_out<<<dim3(MM / 32, FF / 32, BB), dim3(32, 8)>>>(out);
}

// round 5
// speedup vs baseline: 1.5065x; 1.5065x over previous
#include <cuda_runtime.h>

// Problem shape (fixed by the dataset)
#define BB 4
#define NN 8192
#define MM 2048
#define FF 256
#define KK 16
#define CH (3 + FF)   // 259 output channels

// Scratch (static __device__ — no allocations allowed)
__device__ float4 g_pts4[BB * NN];               // packed xyz + |p|^2, 512KB
__device__ int    g_idx [BB * MM * KK];          // neighbor indices
__device__ float  g_w   [BB * MM * KK];          // softmax weights
__device__ float  g_T   [(size_t)BB * NN * FF];  // features transposed (B,N,F), 33.5MB

// ---------------------------------------------------------------------------
// K0: pack point cloud (B,3,N) -> float4 (x,y,z,|p|^2)
// ---------------------------------------------------------------------------
__global__ void k_pack(const float* __restrict__ pc) {
    int i = blockIdx.x * blockDim.x + threadIdx.x;
    if (i >= BB * NN) return;
    int b = i / NN, n = i - b * NN;
    const float* base = pc + (size_t)b * 3 * NN;
    float x = base[n], y = base[NN + n], z = base[2 * NN + n];
    g_pts4[i] = make_float4(x, y, z, fmaf(x, x, fmaf(y, y, z * z)));
}

// ---------------------------------------------------------------------------
// K1: warp-per-query KNN (k=16) + softmax weights + projected points.
// Lanes 0..15 hold a distributed ascending-sorted (dist', idx) list where
// dist' = |p|^2 - 2 q.p  (= true dist^2 - |q|^2; same ordering, and softmax
// uses only differences so the constant offset cancels exactly).
// 4x32-point unroll: 4 independent LDG.128 per iter, 3 FMA per distance.
// ---------------------------------------------------------------------------
__global__ void k_knn(const float* __restrict__ qc,
                      const float* __restrict__ temp,
                      float* __restrict__ out) {
    const unsigned FULL = 0xFFFFFFFFu;
    int gw   = (blockIdx.x * blockDim.x + threadIdx.x) >> 5;  // query id
    int lane = threadIdx.x & 31;
    int b = gw / MM, m = gw - b * MM;

    const float* qb = qc + (size_t)b * 3 * MM;
    float n2x = -2.0f * qb[m];
    float n2y = -2.0f * qb[MM + m];
    float n2z = -2.0f * qb[2 * MM + m];

    const float4* pts = g_pts4 + (size_t)b * NN;

    float ld  = __int_as_float(0x7f800000);  // +inf
    int   li  = 0;
    float tau = ld;                          // current worst of the 16 (list[15])

#define PROCESS(dv, boff)                                                   \
    {                                                                        \
        unsigned ball = __ballot_sync(FULL, (dv) < tau);                     \
        while (ball) {                                                       \
            int src = __ffs(ball) - 1;                                       \
            ball &= ball - 1;                                                \
            float dc = __shfl_sync(FULL, (dv), src);                         \
            if (dc < tau) {                                                  \
                int ic = (boff) + src;                                       \
                unsigned less = __ballot_sync(FULL, (lane < KK) && (ld < dc));\
                int pos = __popc(less);                                      \
                float pld = __shfl_up_sync(FULL, ld, 1);                     \
                int   pli = __shfl_up_sync(FULL, li, 1);                     \
                if (lane < KK) {                                             \
                    if (lane > pos)       { ld = pld; li = pli; }            \
                    else if (lane == pos) { ld = dc;  li = ic;  }            \
                }                                                            \
                tau = __shfl_sync(FULL, ld, KK - 1);                         \
            }                                                                \
        }                                                                    \
    }

    for (int base = 0; base < NN; base += 128) {
        float4 p0 = pts[base +       lane];
        float4 p1 = pts[base +  32 + lane];
        float4 p2 = pts[base +  64 + lane];
        float4 p3 = pts[base +  96 + lane];
        float d0 = fmaf(p0.x, n2x, fmaf(p0.y, n2y, fmaf(p0.z, n2z, p0.w)));
        float d1 = fmaf(p1.x, n2x, fmaf(p1.y, n2y, fmaf(p1.z, n2z, p1.w)));
        float d2 = fmaf(p2.x, n2x, fmaf(p2.y, n2y, fmaf(p2.z, n2z, p2.w)));
        float d3 = fmaf(p3.x, n2x, fmaf(p3.y, n2y, fmaf(p3.z, n2z, p3.w)));
        PROCESS(d0, base);
        PROCESS(d1, base + 32);
        PROCESS(d2, base + 64);
        PROCESS(d3, base + 96);
    }
#undef PROCESS

    // softmax(-(d - dmin)/sigma) over the 16 neighbors (offset cancels)
    float tv    = *temp;
    float sigma = fmaxf(tv * tv, 1e-4f);
    float dmin  = __shfl_sync(FULL, ld, 0);  // ascending list -> lane0 is min
    float e = (lane < KK) ? __expf((dmin - ld) / sigma) : 0.0f;
    float s = e;
    #pragma unroll
    for (int off = 16; off >= 1; off >>= 1) s += __shfl_xor_sync(FULL, s, off);
    float w = e / s;

    if (lane < KK) {
        g_idx[gw * KK + lane] = li;
        g_w  [gw * KK + lane] = w;
    }

    // projected points = sum_j w_j * p_j
    float4 gp = make_float4(0.f, 0.f, 0.f, 0.f);
    if (lane < KK) gp = pts[li];
    float sx = w * gp.x, sy = w * gp.y, sz = w * gp.z;
    #pragma unroll
    for (int off = 16; off >= 1; off >>= 1) {
        sx += __shfl_xor_sync(FULL, sx, off);
        sy += __shfl_xor_sync(FULL, sy, off);
        sz += __shfl_xor_sync(FULL, sz, off);
    }
    if (lane == 0) {
        float* ob = out + (size_t)b * CH * MM;
        ob[m]          = sx;
        ob[MM + m]     = sy;
        ob[2 * MM + m] = sz;
    }
}

// ---------------------------------------------------------------------------
// K2: transpose features (B,F,N) -> (B,N,F), tiled 32x32
// ---------------------------------------------------------------------------
__global__ void k_transpose(const float* __restrict__ feat) {
    __shared__ float tile[32][33];
    int b  = blockIdx.z;
    int n0 = blockIdx.x * 32, f0 = blockIdx.y * 32;
    const float* fb = feat + (size_t)b * FF * NN;
    #pragma unroll
    for (int yy = threadIdx.y; yy < 32; yy += 8)
        tile[yy][threadIdx.x] = fb[(size_t)(f0 + yy) * NN + n0 + threadIdx.x];
    __syncthreads();
    float* Tb = g_T + (size_t)b * NN * FF;
    #pragma unroll
    for (int yy = threadIdx.y; yy < 32; yy += 8)
        Tb[(size_t)(n0 + yy) * FF + f0 + threadIdx.x] = tile[threadIdx.x][yy];
}

// ---------------------------------------------------------------------------
// K3 (fused gather + output transpose): one block per (32-query, 32-feature,
// batch) tile. float4 gathers from g_T rows (coalesced, L2-resident), weighted
// accumulate, conflict-free smem transpose, channel-major coalesced store.
// ---------------------------------------------------------------------------
__global__ void k_gather_out(float* __restrict__ out) {
    __shared__ int   sidx[32][KK];
    __shared__ float sw  [32][KK];
    __shared__ float tile[32][33];   // [f_in_tile][query]

    int tid = threadIdx.x;           // 256 threads
    int m0 = blockIdx.x * 32;
    int f0 = blockIdx.y * 32;
    int b  = blockIdx.z;

    // load the 32 queries' neighbor lists: 512 idx + 512 w
    {
        int base = (b * MM + m0) * KK;
        #pragma unroll
        for (int t = tid; t < 32 * KK; t += 256) {
            ((int*)sidx)[t]   = g_idx[base + t];
            ((float*)sw)[t]   = g_w  [base + t];
        }
    }
    __syncthreads();

    // accumulate: thread -> (query qi = tid>>3, float4 chunk xq = tid&7)
    int qi = tid >> 3;
    int xq = tid & 7;
    const float4* Tb4 = (const float4*)(g_T + (size_t)b * NN * FF) + (f0 >> 2) + xq;
    float4 acc = make_float4(0.f, 0.f, 0.f, 0.f);
    #pragma unroll
    for (int j = 0; j < KK; j++) {
        float  wj = sw[qi][j];
        float4 v  = Tb4[(size_t)sidx[qi][j] * (FF / 4)];
        acc.x = fmaf(wj, v.x, acc.x);
        acc.y = fmaf(wj, v.y, acc.y);
        acc.z = fmaf(wj, v.z, acc.z);
        acc.w = fmaf(wj, v.w, acc.w);
    }
    // tile[4*xq+j][qi]: bank = (4*xq + j + qi) mod 32 -> conflict-free
    tile[4 * xq + 0][qi] = acc.x;
    tile[4 * xq + 1][qi] = acc.y;
    tile[4 * xq + 2][qi] = acc.z;
    tile[4 * xq + 3][qi] = acc.w;
    __syncthreads();

    // write channel-major: thread -> (m index x = tid&31, row group yy = tid>>5)
    int x  = tid & 31;
    int y0 = tid >> 5;
    float* dst = out + (size_t)b * CH * MM;
    #pragma unroll
    for (int r = 0; r < 4; r++) {
        int f = y0 + r * 8;
        dst[(size_t)(3 + f0 + f) * MM + m0 + x] = tile[f][x];
    }
}

// ---------------------------------------------------------------------------
extern "C" void kernel_launch(void* const* d_in, const int* in_sizes, int n_in,
                              void* d_out, int out_size) {
    (void)in_sizes; (void)n_in; (void)out_size;
    const float* pc   = (const float*)d_in[0];  // (B,3,N)
    const float* qc   = (const float*)d_in[1];  // (B,3,M)
    const float* feat = (const float*)d_in[2];  // (B,F,N)
    const float* temp = (const float*)d_in[3];  // scalar
    float* out = (float*)d_out;                 // (B,259,M)

    k_pack<<<(BB * NN + 255) / 256, 256>>>(pc);
    k_knn<<<(BB * MM) / 8, 256>>>(qc, temp, out);
    k_transpose<<<dim3(NN / 32, FF / 32, BB), dim3(32, 8)>>>(feat);
    k_gather_out<<<dim3(MM / 32, FF / 32, BB), 256>>>(out);
}